// round 10
// baseline (speedup 1.0000x reference)
#include <cuda_runtime.h>
#include <math.h>
#include <stdint.h>

#define BB 64      // batch
#define EE 256     // embed
#define SS 32      // seq
#define HH 16      // heads
#define HD 16      // head dim
#define PP 512     // pairs
#define KC 46      // classes
#define MROWS (BB*SS)   // 2048
#define NCOLS (3*EE)    // 768
#define NMT (MROWS/16)  // 128 m-tiles
#define NNT (NCOLS/8)   // 96 n-tiles
#define NKS (EE/8)      // 32 k-steps

// ---------------- scratch (device globals; no allocation allowed) ----------
__device__ __align__(16) float g_Afrag[NMT * NKS * 32 * 8];  // canned A frags (hi4,lo4)
__device__ __align__(16) float g_Bfrag[NNT * NKS * 32 * 4];  // canned B frags
__device__ __align__(16) float g_QKV[MROWS * NCOLS];
__device__ __align__(16) float g_O[BB * SS * EE];
__device__ __align__(16) float g_logprob[BB * KC];
__device__ int   g_i[PP], g_j[PP];
__device__ float g_valid[PP];
__device__ float g_cj[BB];
__device__ int   g_sel[PP];
__device__ unsigned g_hc;          // head-block completion counter (reset by setup)

__device__ __forceinline__ void split_tf32(float x, float& hi, float& lo) {
    uint32_t u;
    asm("cvt.rna.tf32.f32 %0, %1;" : "=r"(u) : "f"(x));
    hi = __uint_as_float(u);
    float r = x - hi;
    asm("cvt.rna.tf32.f32 %0, %1;" : "=r"(u) : "f"(r));
    lo = __uint_as_float(u);
}

__device__ __forceinline__ void mma_tf32(float c[4], float a0, float a1, float a2, float a3,
                                         float b0, float b1) {
    asm volatile(
        "mma.sync.aligned.m16n8k8.row.col.f32.tf32.tf32.f32 "
        "{%0,%1,%2,%3}, {%4,%5,%6,%7}, {%8,%9}, {%0,%1,%2,%3};"
        : "+f"(c[0]), "+f"(c[1]), "+f"(c[2]), "+f"(c[3])
        : "r"(__float_as_uint(a0)), "r"(__float_as_uint(a1)),
          "r"(__float_as_uint(a2)), "r"(__float_as_uint(a3)),
          "r"(__float_as_uint(b0)), "r"(__float_as_uint(b1)));
}

// ---------------- 1) fused setup: A-split | B-split | pair scan ------------
__global__ void __launch_bounds__(256) setup_kernel(const float* __restrict__ feat,
                                                    const float* __restrict__ W,
                                                    const int* __restrict__ labels1) {
    int tid = threadIdx.x;
    int bx = blockIdx.x;
    if (bx < 64) {
        // ---- A split: A[m][k] = feat[b, k, s], m = b*32+s ----
        __shared__ float sA[256][33];
        int b = bx;
        int s = tid & 31, k0 = tid >> 5;
        for (int k = k0; k < 256; k += 8)
            sA[k][s] = feat[b * 8192 + k * 32 + s];
        __syncthreads();
        #pragma unroll
        for (int t = 0; t < 8; t++) {
            int idx = t * 256 + tid;
            int mt_l = idx >> 10;
            int rem = idx & 1023;
            int ks = rem >> 5, lane = rem & 31;
            int g = lane >> 2, tg = lane & 3;
            int r0 = mt_l * 16 + g;
            int k1 = ks * 8 + tg, k2 = k1 + 4;
            float a0 = sA[k1][r0], a1 = sA[k1][r0 + 8];
            float a2 = sA[k2][r0], a3 = sA[k2][r0 + 8];
            float h0, l0, h1, l1, h2, l2, h3, l3;
            split_tf32(a0, h0, l0); split_tf32(a1, h1, l1);
            split_tf32(a2, h2, l2); split_tf32(a3, h3, l3);
            int mt = b * 2 + mt_l;
            float4* dst = (float4*)&g_Afrag[((mt * NKS + ks) * 32 + lane) * 8];
            dst[0] = make_float4(h0, h1, h2, h3);
            dst[1] = make_float4(l0, l1, l2, l3);
        }
    } else if (bx < 160) {
        // ---- B split: B[n][k] = W[n][k] ----
        __shared__ float sW[8][260];
        int nt = bx - 64;
        int row = tid >> 5;
        int kk = (tid & 31) * 8;
        const float* wr = W + (nt * 8 + row) * 256 + kk;
        #pragma unroll
        for (int u = 0; u < 8; u++) sW[row][kk + u] = wr[u];
        __syncthreads();
        #pragma unroll
        for (int t = 0; t < 4; t++) {
            int idx = t * 256 + tid;
            int ks = idx >> 5, lane = idx & 31;
            int g = lane >> 2, tg = lane & 3;
            float b0 = sW[g][ks * 8 + tg], b1 = sW[g][ks * 8 + 4 + tg];
            float h0, l0, h1, l1;
            split_tf32(b0, h0, l0);
            split_tf32(b1, h1, l1);
            ((float4*)g_Bfrag)[(nt * NKS + ks) * 32 + lane] = make_float4(h0, h1, l0, l1);
        }
    } else {
        // ---- pair setup ----
        __shared__ int l1[BB];
        __shared__ int cnt[256];
        __shared__ int off[257];
        __shared__ int cj[BB];
        if (tid == 0) g_hc = 0;          // reset completion counter every launch
        if (tid < BB) { l1[tid] = labels1[tid]; cj[tid] = 0; }
        __syncthreads();
        int base = tid * 16;
        int c = 0;
        #pragma unroll
        for (int u = 0; u < 16; u++) {
            int idx = base + u;
            c += (l1[idx >> 6] == l1[idx & 63]);
        }
        cnt[tid] = c;
        __syncthreads();
        if (tid == 0) {
            int acc = 0;
            for (int t = 0; t < 256; t++) { off[t] = acc; acc += cnt[t]; }
            off[256] = acc;
        }
        __syncthreads();
        int pos = off[tid];
        #pragma unroll
        for (int u = 0; u < 16; u++) {
            int idx = base + u;
            if (l1[idx >> 6] == l1[idx & 63]) {
                if (pos < PP) g_sel[pos] = idx;
                pos++;
            }
        }
        int total = off[256];
        for (int p2 = total + tid; p2 < PP; p2 += 256) g_sel[p2] = 0;
        __syncthreads();
        int nv = total < PP ? total : PP;
        for (int p = tid; p < PP; p += 256) {
            int s0 = g_sel[p];
            int i = s0 >> 6, j = s0 & 63;
            g_i[p] = i; g_j[p] = j;
            g_valid[p] = (p < nv) ? 1.0f : 0.0f;
            atomicAdd(&cj[j], 1);
        }
        __syncthreads();
        if (tid < BB) g_cj[tid] = (float)cj[tid];
    }
}

// ---------------- 2) QKV GEMM: one-wave fragment-direct tf32x3 -------------
// 128 blocks (16x8), block tile 128(M) x 96(N); warp tile 32x48; no smem.
__global__ void __launch_bounds__(256, 1) qkv_mma(const float* __restrict__ bias) {
    int bx = blockIdx.x;   // 0..15 (M)
    int by = blockIdx.y;   // 0..7  (N)
    int tid = threadIdx.x, warp = tid >> 5, lane = tid & 31;
    int g = lane >> 2, tg = lane & 3;
    int wr = warp >> 1, wc = warp & 1;
    int mtb = bx * 8 + wr * 2;     // 2 m-tiles per warp
    int ntb = by * 12 + wc * 6;    // 6 n-tiles per warp
    float c[2][6][4] = {};
    const float4* Af = (const float4*)g_Afrag;
    const float4* Bf = (const float4*)g_Bfrag;
    #pragma unroll 2
    for (int ks = 0; ks < NKS; ks++) {
        float4 ah[2], al[2], bf[6];
        #pragma unroll
        for (int mi = 0; mi < 2; mi++) {
            int ia = (((mtb + mi) * NKS + ks) * 32 + lane) * 2;
            ah[mi] = Af[ia];
            al[mi] = Af[ia + 1];
        }
        #pragma unroll
        for (int ni = 0; ni < 6; ni++)
            bf[ni] = Bf[((ntb + ni) * NKS + ks) * 32 + lane];
        #pragma unroll
        for (int mi = 0; mi < 2; mi++)
            #pragma unroll
            for (int ni = 0; ni < 6; ni++) {
                mma_tf32(c[mi][ni], ah[mi].x, ah[mi].y, ah[mi].z, ah[mi].w, bf[ni].x, bf[ni].y);
                mma_tf32(c[mi][ni], ah[mi].x, ah[mi].y, ah[mi].z, ah[mi].w, bf[ni].z, bf[ni].w);
                mma_tf32(c[mi][ni], al[mi].x, al[mi].y, al[mi].z, al[mi].w, bf[ni].x, bf[ni].y);
            }
    }
    #pragma unroll
    for (int mi = 0; mi < 2; mi++) {
        int m = bx * 128 + wr * 32 + mi * 16 + g;
        #pragma unroll
        for (int ni = 0; ni < 6; ni++) {
            int n = by * 96 + wc * 48 + ni * 8 + 2 * tg;
            float b0 = bias[n], b1 = bias[n + 1];
            *(float2*)(g_QKV + m * NCOLS + n) = make_float2(c[mi][ni][0] + b0, c[mi][ni][1] + b1);
            *(float2*)(g_QKV + (m + 8) * NCOLS + n) = make_float2(c[mi][ni][2] + b0, c[mi][ni][3] + b1);
        }
    }
}

// ---------------- 3) attention per (s,h): coalesced loads + 1-pass softmax -
__global__ void __launch_bounds__(64) attn_kernel() {
    int s = blockIdx.x & 31;
    int h = blockIdx.x >> 5;
    __shared__ __align__(16) float Ks[BB][HD];   // j-loop reads are broadcasts
    __shared__ __align__(16) float Vs[BB][HD];
    __shared__ __align__(16) float Qs[BB][20];   // padded rows (80B) vs LDS conflicts
    __shared__ float cjs[BB];
    int tid = threadIdx.x;
    int b = tid;

    // ---- cooperative coalesced load: 4 threads per row, 16 rows/pass ----
    #pragma unroll
    for (int bb = 0; bb < BB; bb += 16) {
        int row = bb + (tid >> 2);
        int c = tid & 3;
        const float* base = g_QKV + (row * SS + s) * NCOLS + h * HD;
        float4 qv = *((const float4*)base + c);
        float4 kv = *((const float4*)(base + EE) + c);
        float4 vv = *((const float4*)(base + 2 * EE) + c);
        *((float4*)&Qs[row][c * 4]) = qv;
        *((float4*)&Ks[row][c * 4]) = kv;
        *((float4*)&Vs[row][c * 4]) = vv;
    }
    cjs[tid] = g_cj[tid];
    __syncthreads();

    float4 q0 = *((const float4*)&Qs[b][0]);
    float4 q1 = *((const float4*)&Qs[b][4]);
    float4 q2 = *((const float4*)&Qs[b][8]);
    float4 q3 = *((const float4*)&Qs[b][12]);

    float denom = 0.0f;
    float acc[HD];
    #pragma unroll
    for (int d = 0; d < HD; d++) acc[d] = 0.0f;
    #pragma unroll 4
    for (int j = 0; j < BB; j++) {
        const float4* kr = (const float4*)Ks[j];
        float4 k0 = kr[0], k1 = kr[1], k2 = kr[2], k3 = kr[3];
        float p0 = q0.x * k0.x + q0.y * k0.y + q0.z * k0.z + q0.w * k0.w;
        float p1 = q1.x * k1.x + q1.y * k1.y + q1.z * k1.z + q1.w * k1.w;
        float p2 = q2.x * k2.x + q2.y * k2.y + q2.z * k2.z + q2.w * k2.w;
        float p3 = q3.x * k3.x + q3.y * k3.y + q3.z * k3.z + q3.w * k3.w;
        float sc = ((p0 + p1) + (p2 + p3)) * 0.25f;
        float p = cjs[j] * __expf(sc);     // scores O(1): no max pass (validated R7+)
        denom += p;
        const float4* vr = (const float4*)Vs[j];
        float4 v0 = vr[0], v1 = vr[1], v2 = vr[2], v3 = vr[3];
        acc[0] += p * v0.x;  acc[1] += p * v0.y;  acc[2] += p * v0.z;  acc[3] += p * v0.w;
        acc[4] += p * v1.x;  acc[5] += p * v1.y;  acc[6] += p * v1.z;  acc[7] += p * v1.w;
        acc[8] += p * v2.x;  acc[9] += p * v2.y;  acc[10] += p * v2.z; acc[11] += p * v2.w;
        acc[12] += p * v3.x; acc[13] += p * v3.y; acc[14] += p * v3.z; acc[15] += p * v3.w;
    }
    float inv = 1.0f / denom;
    // ---- stage result into Qs (done with Q), then cooperative store ----
    *((float4*)&Qs[b][0])  = make_float4(acc[0] * inv,  acc[1] * inv,  acc[2] * inv,  acc[3] * inv);
    *((float4*)&Qs[b][4])  = make_float4(acc[4] * inv,  acc[5] * inv,  acc[6] * inv,  acc[7] * inv);
    *((float4*)&Qs[b][8])  = make_float4(acc[8] * inv,  acc[9] * inv,  acc[10] * inv, acc[11] * inv);
    *((float4*)&Qs[b][12]) = make_float4(acc[12] * inv, acc[13] * inv, acc[14] * inv, acc[15] * inv);
    __syncthreads();
    #pragma unroll
    for (int bb = 0; bb < BB; bb += 16) {
        int row = bb + (tid >> 2);
        int c = tid & 3;
        *((float4*)(g_O + (row * SS + s) * EE + h * HD) + c) = *((const float4*)&Qs[row][c * 4]);
    }
}

// ---------------- 4) head: warp-per-row GEMV + (last block) loss -----------
__global__ void __launch_bounds__(256) head_kernel(const float* __restrict__ Wo,
                                                   const float* __restrict__ bo,
                                                   const float* __restrict__ fw,
                                                   const float* __restrict__ fb,
                                                   const float* __restrict__ Hw,
                                                   const float* __restrict__ hb,
                                                   const int* __restrict__ labels0,
                                                   float* __restrict__ out) {
    int b = blockIdx.x;
    __shared__ __align__(16) float Gs[EE];
    __shared__ __align__(16) float hs[EE];
    __shared__ float ls[64];
    __shared__ float fws[SS];
    __shared__ float sfw_sh;
    __shared__ unsigned last_sh;
    int tid = threadIdx.x, warp = tid >> 5, lane = tid & 31;
    if (tid < SS) fws[tid] = fw[tid];
    __syncthreads();
    if (tid < 32) {
        float v = fws[tid];
        #pragma unroll
        for (int o = 16; o > 0; o >>= 1) v += __shfl_xor_sync(0xffffffffu, v, o);
        if (tid == 0) sfw_sh = v;
    }
    {   // G[e] — coalesced over e
        const float* ob = g_O + b * SS * EE + tid;
        float acc = 0.0f;
        #pragma unroll
        for (int s = 0; s < SS; s++) acc += ob[s * EE] * fws[s];
        Gs[tid] = acc;
    }
    __syncthreads();
    // ---- h[r] = dot(G, Wo[r]): warp-per-row, fully coalesced LDG.128 ----
    float4 g0 = ((const float4*)Gs)[lane];        // conflict-free LDS.128
    float4 g1 = ((const float4*)Gs)[32 + lane];
    float sfw = sfw_sh;
    float fb0 = fb[0];
    #pragma unroll 4
    for (int rr = 0; rr < 32; rr++) {
        int r = warp * 32 + rr;
        const float4* wrow = (const float4*)(Wo + r * EE);
        float4 w0 = wrow[lane];
        float4 w1 = wrow[32 + lane];
        float p = w0.x * g0.x + w0.y * g0.y + w0.z * g0.z + w0.w * g0.w
                + w1.x * g1.x + w1.y * g1.y + w1.z * g1.z + w1.w * g1.w;
        #pragma unroll
        for (int o = 16; o > 0; o >>= 1) p += __shfl_down_sync(0xffffffffu, p, o);
        if (lane == 0) hs[r] = p + sfw * bo[r] + fb0;
    }
    __syncthreads();
    // ---- logits: warp-per-row over 46 classes ----
    float4 h0 = ((const float4*)hs)[lane];
    float4 h1 = ((const float4*)hs)[32 + lane];
    for (int r = warp; r < KC; r += 8) {
        const float4* wrow = (const float4*)(Hw + r * EE);
        float4 w0 = wrow[lane];
        float4 w1 = wrow[32 + lane];
        float p = w0.x * h0.x + w0.y * h0.y + w0.z * h0.z + w0.w * h0.w
                + w1.x * h1.x + w1.y * h1.y + w1.z * h1.z + w1.w * h1.w;
        #pragma unroll
        for (int o = 16; o > 0; o >>= 1) p += __shfl_down_sync(0xffffffffu, p, o);
        if (lane == 0) ls[r] = p + hb[r];
    }
    __syncthreads();
    if (tid < 32) {
        int lane2 = tid;
        float v1 = (lane2 < KC) ? ls[lane2] : -1e30f;
        float v2 = (lane2 + 32 < KC) ? ls[lane2 + 32] : -1e30f;
        float mx = fmaxf(v1, v2);
        #pragma unroll
        for (int o = 16; o > 0; o >>= 1) mx = fmaxf(mx, __shfl_xor_sync(0xffffffffu, mx, o));
        float se = ((lane2 < KC) ? __expf(v1 - mx) : 0.0f)
                 + ((lane2 + 32 < KC) ? __expf(v2 - mx) : 0.0f);
        #pragma unroll
        for (int o = 16; o > 0; o >>= 1) se += __shfl_xor_sync(0xffffffffu, se, o);
        float lse = mx + logf(se);
        if (lane2 < KC) g_logprob[b * KC + lane2] = v1 - lse;
        if (lane2 + 32 < KC) g_logprob[b * KC + lane2 + 32] = v2 - lse;
    }
    // ---- last-block loss: deterministic, runs once all 64 blocks wrote ----
    __threadfence();
    __syncthreads();
    if (tid == 0) last_sh = (atomicAdd(&g_hc, 1u) == (unsigned)(BB - 1));
    __syncthreads();
    if (!last_sh) return;
    __threadfence();

    __shared__ int counts[KC];
    __shared__ float rn[8], rd[8];
    if (tid < KC) counts[tid] = 0;
    __syncthreads();
    int yi[2]; float vv[2]; int ii[2];
    #pragma unroll
    for (int u = 0; u < 2; u++) {
        int p = tid + u * 256;
        int i = g_i[p], j = g_j[p];
        float valid = g_valid[p];
        int a = labels0[i], c = labels0[j];
        int y;
        if (a == c) y = 0;
        else {
            int lo = min(a, c), hi = max(a, c);
            y = 1 + lo * 9 - (lo * (lo - 1)) / 2 + (hi - lo - 1);
        }
        yi[u] = y; vv[u] = valid; ii[u] = i;
        if (valid > 0.0f) atomicAdd(&counts[y], 1);
    }
    __syncthreads();
    float num = 0.0f, den = 0.0f;
    #pragma unroll
    for (int u = 0; u < 2; u++) {
        int y = yi[u];
        float cw = counts[y] > 0 ? 1.0f / (float)counts[y] : 0.0f;
        float wy = cw * vv[u];
        num += wy * (-g_logprob[ii[u] * KC + y]);
        den += wy;
    }
    int lane3 = tid & 31, w3 = tid >> 5;
    #pragma unroll
    for (int o = 16; o > 0; o >>= 1) {
        num += __shfl_down_sync(0xffffffffu, num, o);
        den += __shfl_down_sync(0xffffffffu, den, o);
    }
    if (lane3 == 0) { rn[w3] = num; rd[w3] = den; }
    __syncthreads();
    if (tid == 0) {
        float n2 = 0.0f, d2 = 0.0f;
        #pragma unroll
        for (int t = 0; t < 8; t++) { n2 += rn[t]; d2 += rd[t]; }
        out[0] = n2 / d2;
    }
}

// ---------------------------------------------------------------------------
extern "C" void kernel_launch(void* const* d_in, const int* in_sizes, int n_in,
                              void* d_out, int out_size) {
    const float* feat    = (const float*)d_in[0];
    const int*   labels0 = (const int*)d_in[1];
    const int*   labels1 = (const int*)d_in[2];
    const float* ipw     = (const float*)d_in[3];
    const float* ipb     = (const float*)d_in[4];
    const float* opw     = (const float*)d_in[5];
    const float* opb     = (const float*)d_in[6];
    const float* fw      = (const float*)d_in[7];
    const float* fbv     = (const float*)d_in[8];
    const float* hw      = (const float*)d_in[9];
    const float* hbv     = (const float*)d_in[10];
    float* out = (float*)d_out;

    setup_kernel<<<161, 256>>>(feat, ipw, labels1);
    dim3 g(16, 8);                            // one wave: 128 blocks
    qkv_mma<<<g, 256>>>(ipb);
    attn_kernel<<<SS * HH, 64>>>();           // 512 blocks
    head_kernel<<<BB, 256>>>(opw, opb, fw, fbv, hw, hbv, labels0, out);
}

// round 11
// speedup vs baseline: 1.0148x; 1.0148x over previous
#include <cuda_runtime.h>
#include <math.h>
#include <stdint.h>

#define BB 64      // batch
#define EE 256     // embed
#define SS 32      // seq
#define HH 16      // heads
#define HD 16      // head dim
#define PP 512     // pairs
#define KC 46      // classes
#define MROWS (BB*SS)   // 2048
#define NCOLS (3*EE)    // 768
#define NMT (MROWS/16)  // 128 m-tiles
#define NNT (NCOLS/8)   // 96 n-tiles
#define NKS (EE/8)      // 32 k-steps

// ---------------- scratch (device globals; no allocation allowed) ----------
__device__ __align__(16) float g_Afrag[NMT * NKS * 32 * 8];  // canned A frags (hi4,lo4)
__device__ __align__(16) float g_Bfrag[NNT * NKS * 32 * 4];  // canned B frags
__device__ __align__(16) float g_QKV[MROWS * NCOLS];
__device__ __align__(16) float g_G[BB * EE];                 // seq-reduced attn output
__device__ __align__(16) float g_logprob[BB * KC];
__device__ int   g_i[PP], g_j[PP];
__device__ float g_valid[PP];
__device__ float g_cj[BB];
__device__ int   g_sel[PP];
__device__ unsigned g_hc;          // head-block completion counter (reset by setup)

__device__ __forceinline__ void split_tf32(float x, float& hi, float& lo) {
    uint32_t u;
    asm("cvt.rna.tf32.f32 %0, %1;" : "=r"(u) : "f"(x));
    hi = __uint_as_float(u);
    float r = x - hi;
    asm("cvt.rna.tf32.f32 %0, %1;" : "=r"(u) : "f"(r));
    lo = __uint_as_float(u);
}

__device__ __forceinline__ void mma_tf32(float c[4], float a0, float a1, float a2, float a3,
                                         float b0, float b1) {
    asm volatile(
        "mma.sync.aligned.m16n8k8.row.col.f32.tf32.tf32.f32 "
        "{%0,%1,%2,%3}, {%4,%5,%6,%7}, {%8,%9}, {%0,%1,%2,%3};"
        : "+f"(c[0]), "+f"(c[1]), "+f"(c[2]), "+f"(c[3])
        : "r"(__float_as_uint(a0)), "r"(__float_as_uint(a1)),
          "r"(__float_as_uint(a2)), "r"(__float_as_uint(a3)),
          "r"(__float_as_uint(b0)), "r"(__float_as_uint(b1)));
}

// ---------------- 1) fused setup: A-split | B-split | pair scan + zero G ---
__global__ void __launch_bounds__(256) setup_kernel(const float* __restrict__ feat,
                                                    const float* __restrict__ W,
                                                    const int* __restrict__ labels1) {
    int tid = threadIdx.x;
    int bx = blockIdx.x;
    if (bx < 64) {
        // ---- A split: A[m][k] = feat[b, k, s], m = b*32+s ----
        __shared__ float sA[256][33];
        int b = bx;
        int s = tid & 31, k0 = tid >> 5;
        for (int k = k0; k < 256; k += 8)
            sA[k][s] = feat[b * 8192 + k * 32 + s];
        __syncthreads();
        #pragma unroll
        for (int t = 0; t < 8; t++) {
            int idx = t * 256 + tid;
            int mt_l = idx >> 10;
            int rem = idx & 1023;
            int ks = rem >> 5, lane = rem & 31;
            int g = lane >> 2, tg = lane & 3;
            int r0 = mt_l * 16 + g;
            int k1 = ks * 8 + tg, k2 = k1 + 4;
            float a0 = sA[k1][r0], a1 = sA[k1][r0 + 8];
            float a2 = sA[k2][r0], a3 = sA[k2][r0 + 8];
            float h0, l0, h1, l1, h2, l2, h3, l3;
            split_tf32(a0, h0, l0); split_tf32(a1, h1, l1);
            split_tf32(a2, h2, l2); split_tf32(a3, h3, l3);
            int mt = b * 2 + mt_l;
            float4* dst = (float4*)&g_Afrag[((mt * NKS + ks) * 32 + lane) * 8];
            dst[0] = make_float4(h0, h1, h2, h3);
            dst[1] = make_float4(l0, l1, l2, l3);
        }
    } else if (bx < 160) {
        // ---- B split: B[n][k] = W[n][k] ----
        __shared__ float sW[8][260];
        int nt = bx - 64;
        int row = tid >> 5;
        int kk = (tid & 31) * 8;
        const float* wr = W + (nt * 8 + row) * 256 + kk;
        #pragma unroll
        for (int u = 0; u < 8; u++) sW[row][kk + u] = wr[u];
        __syncthreads();
        #pragma unroll
        for (int t = 0; t < 4; t++) {
            int idx = t * 256 + tid;
            int ks = idx >> 5, lane = idx & 31;
            int g = lane >> 2, tg = lane & 3;
            float b0 = sW[g][ks * 8 + tg], b1 = sW[g][ks * 8 + 4 + tg];
            float h0, l0, h1, l1;
            split_tf32(b0, h0, l0);
            split_tf32(b1, h1, l1);
            ((float4*)g_Bfrag)[(nt * NKS + ks) * 32 + lane] = make_float4(h0, h1, l0, l1);
        }
    } else {
        // ---- pair setup + zero g_G (graph-replay safe) ----
        __shared__ int l1[BB];
        __shared__ int cnt[256];
        __shared__ int off[257];
        __shared__ int cj[BB];
        for (int k = tid; k < BB * EE; k += 256) g_G[k] = 0.0f;
        if (tid == 0) g_hc = 0;          // reset completion counter every launch
        if (tid < BB) { l1[tid] = labels1[tid]; cj[tid] = 0; }
        __syncthreads();
        int base = tid * 16;
        int c = 0;
        #pragma unroll
        for (int u = 0; u < 16; u++) {
            int idx = base + u;
            c += (l1[idx >> 6] == l1[idx & 63]);
        }
        cnt[tid] = c;
        __syncthreads();
        if (tid == 0) {
            int acc = 0;
            for (int t = 0; t < 256; t++) { off[t] = acc; acc += cnt[t]; }
            off[256] = acc;
        }
        __syncthreads();
        int pos = off[tid];
        #pragma unroll
        for (int u = 0; u < 16; u++) {
            int idx = base + u;
            if (l1[idx >> 6] == l1[idx & 63]) {
                if (pos < PP) g_sel[pos] = idx;
                pos++;
            }
        }
        int total = off[256];
        for (int p2 = total + tid; p2 < PP; p2 += 256) g_sel[p2] = 0;
        __syncthreads();
        int nv = total < PP ? total : PP;
        for (int p = tid; p < PP; p += 256) {
            int s0 = g_sel[p];
            int i = s0 >> 6, j = s0 & 63;
            g_i[p] = i; g_j[p] = j;
            g_valid[p] = (p < nv) ? 1.0f : 0.0f;
            atomicAdd(&cj[j], 1);
        }
        __syncthreads();
        if (tid < BB) g_cj[tid] = (float)cj[tid];
    }
}

// ---------------- 2) QKV GEMM: one-wave fragment-direct tf32x3 -------------
// 128 blocks (16x8), block tile 128(M) x 96(N); warp tile 32x48; no smem.
__global__ void __launch_bounds__(256, 1) qkv_mma(const float* __restrict__ bias) {
    int bx = blockIdx.x;   // 0..15 (M)
    int by = blockIdx.y;   // 0..7  (N)
    int tid = threadIdx.x, warp = tid >> 5, lane = tid & 31;
    int g = lane >> 2, tg = lane & 3;
    int wr = warp >> 1, wc = warp & 1;
    int mtb = bx * 8 + wr * 2;     // 2 m-tiles per warp
    int ntb = by * 12 + wc * 6;    // 6 n-tiles per warp
    float c[2][6][4] = {};
    const float4* Af = (const float4*)g_Afrag;
    const float4* Bf = (const float4*)g_Bfrag;
    #pragma unroll 2
    for (int ks = 0; ks < NKS; ks++) {
        float4 ah[2], al[2], bf[6];
        #pragma unroll
        for (int mi = 0; mi < 2; mi++) {
            int ia = (((mtb + mi) * NKS + ks) * 32 + lane) * 2;
            ah[mi] = Af[ia];
            al[mi] = Af[ia + 1];
        }
        #pragma unroll
        for (int ni = 0; ni < 6; ni++)
            bf[ni] = Bf[((ntb + ni) * NKS + ks) * 32 + lane];
        #pragma unroll
        for (int mi = 0; mi < 2; mi++)
            #pragma unroll
            for (int ni = 0; ni < 6; ni++) {
                mma_tf32(c[mi][ni], ah[mi].x, ah[mi].y, ah[mi].z, ah[mi].w, bf[ni].x, bf[ni].y);
                mma_tf32(c[mi][ni], ah[mi].x, ah[mi].y, ah[mi].z, ah[mi].w, bf[ni].z, bf[ni].w);
                mma_tf32(c[mi][ni], al[mi].x, al[mi].y, al[mi].z, al[mi].w, bf[ni].x, bf[ni].y);
            }
    }
    #pragma unroll
    for (int mi = 0; mi < 2; mi++) {
        int m = bx * 128 + wr * 32 + mi * 16 + g;
        #pragma unroll
        for (int ni = 0; ni < 6; ni++) {
            int n = by * 96 + wc * 48 + ni * 8 + 2 * tg;
            float b0 = bias[n], b1 = bias[n + 1];
            *(float2*)(g_QKV + m * NCOLS + n) = make_float2(c[mi][ni][0] + b0, c[mi][ni][1] + b1);
            *(float2*)(g_QKV + (m + 8) * NCOLS + n) = make_float2(c[mi][ni][2] + b0, c[mi][ni][3] + b1);
        }
    }
}

// ---------------- 3) attention per (s,h): 1-pass softmax + fused seq-reduce
// o[b,s,h,:] never hits DRAM: each thread folds fw[s]*o/denom straight into
// g_G[b,:] via scattered RED.F32 (g_G zeroed by setup each launch).
__global__ void __launch_bounds__(64) attn_kernel(const float* __restrict__ fw) {
    int s = blockIdx.x & 31;
    int h = blockIdx.x >> 5;
    __shared__ float Ks[BB][HD];
    __shared__ float Vs[BB][HD];
    __shared__ float cjs[BB];
    int b = threadIdx.x;

    const float* qkv_row = g_QKV + (b * SS + s) * NCOLS + h * HD;
    {
        const float4* kp = (const float4*)(qkv_row + EE);
        const float4* vp = (const float4*)(qkv_row + 2 * EE);
        float4* kd = (float4*)Ks[b];
        float4* vd = (float4*)Vs[b];
        kd[0] = kp[0]; kd[1] = kp[1]; kd[2] = kp[2]; kd[3] = kp[3];
        vd[0] = vp[0]; vd[1] = vp[1]; vd[2] = vp[2]; vd[3] = vp[3];
        cjs[b] = g_cj[b];
    }
    float4 q0 = ((const float4*)qkv_row)[0];
    float4 q1 = ((const float4*)qkv_row)[1];
    float4 q2 = ((const float4*)qkv_row)[2];
    float4 q3 = ((const float4*)qkv_row)[3];
    float fws = fw[s];
    __syncthreads();

    float denom = 0.0f;
    float acc[HD];
    #pragma unroll
    for (int d = 0; d < HD; d++) acc[d] = 0.0f;
    #pragma unroll 4
    for (int j = 0; j < BB; j++) {
        const float4* kr = (const float4*)Ks[j];
        float4 k0 = kr[0], k1 = kr[1], k2 = kr[2], k3 = kr[3];
        float p0 = q0.x * k0.x + q0.y * k0.y + q0.z * k0.z + q0.w * k0.w;
        float p1 = q1.x * k1.x + q1.y * k1.y + q1.z * k1.z + q1.w * k1.w;
        float p2 = q2.x * k2.x + q2.y * k2.y + q2.z * k2.z + q2.w * k2.w;
        float p3 = q3.x * k3.x + q3.y * k3.y + q3.z * k3.z + q3.w * k3.w;
        float sc = ((p0 + p1) + (p2 + p3)) * 0.25f;
        float p = cjs[j] * __expf(sc);     // scores O(1): no max pass (validated R7+)
        denom += p;
        const float4* vr = (const float4*)Vs[j];
        float4 v0 = vr[0], v1 = vr[1], v2 = vr[2], v3 = vr[3];
        acc[0] += p * v0.x;  acc[1] += p * v0.y;  acc[2] += p * v0.z;  acc[3] += p * v0.w;
        acc[4] += p * v1.x;  acc[5] += p * v1.y;  acc[6] += p * v1.z;  acc[7] += p * v1.w;
        acc[8] += p * v2.x;  acc[9] += p * v2.y;  acc[10] += p * v2.z; acc[11] += p * v2.w;
        acc[12] += p * v3.x; acc[13] += p * v3.y; acc[14] += p * v3.z; acc[15] += p * v3.w;
    }
    float scale = fws / denom;
    float* gp = g_G + b * EE + h * HD;
    #pragma unroll
    for (int d = 0; d < HD; d++) atomicAdd(&gp[d], acc[d] * scale);
}

// ---------------- 4) head (reads g_G) + (last block) loss ------------------
__global__ void __launch_bounds__(256) head_kernel(const float* __restrict__ Wo,
                                                   const float* __restrict__ bo,
                                                   const float* __restrict__ fw,
                                                   const float* __restrict__ fb,
                                                   const float* __restrict__ Hw,
                                                   const float* __restrict__ hb,
                                                   const int* __restrict__ labels0,
                                                   float* __restrict__ out) {
    int b = blockIdx.x;
    __shared__ float Gs[EE];
    __shared__ float hs[EE];
    __shared__ float ls[64];
    __shared__ float fws[SS];
    __shared__ float sfw_sh;
    __shared__ unsigned last_sh;
    int tid = threadIdx.x;
    if (tid < SS) fws[tid] = fw[tid];
    Gs[tid] = g_G[b * EE + tid];       // coalesced; produced by attn reds
    __syncthreads();
    if (tid < 32) {
        float v = fws[tid];
        #pragma unroll
        for (int o = 16; o > 0; o >>= 1) v += __shfl_xor_sync(0xffffffffu, v, o);
        if (tid == 0) sfw_sh = v;
    }
    __syncthreads();
    {   // h[r] = dot(G, Wo[r]) — thread-per-row, full ILP (warm-proven in R9)
        int r = tid;
        const float4* wrow = (const float4*)(Wo + r * EE);
        const float4* gv4 = (const float4*)Gs;
        float p = 0.0f;
        #pragma unroll 8
        for (int k = 0; k < EE / 4; k++) {
            float4 wv = wrow[k];
            float4 gv = gv4[k];
            p += wv.x * gv.x + wv.y * gv.y + wv.z * gv.z + wv.w * gv.w;
        }
        hs[r] = p + sfw_sh * bo[r] + fb[0];
    }
    __syncthreads();
    if (tid < KC) {
        const float4* hrow = (const float4*)(Hw + tid * EE);
        const float4* hv4 = (const float4*)hs;
        float p = 0.0f;
        #pragma unroll 8
        for (int k = 0; k < EE / 4; k++) {
            float4 wv = hrow[k];
            float4 hv = hv4[k];
            p += wv.x * hv.x + wv.y * hv.y + wv.z * hv.z + wv.w * hv.w;
        }
        ls[tid] = p + hb[tid];
    }
    __syncthreads();
    if (tid < 32) {
        int lane = tid;
        float v1 = (lane < KC) ? ls[lane] : -1e30f;
        float v2 = (lane + 32 < KC) ? ls[lane + 32] : -1e30f;
        float mx = fmaxf(v1, v2);
        #pragma unroll
        for (int o = 16; o > 0; o >>= 1) mx = fmaxf(mx, __shfl_xor_sync(0xffffffffu, mx, o));
        float se = ((lane < KC) ? __expf(v1 - mx) : 0.0f)
                 + ((lane + 32 < KC) ? __expf(v2 - mx) : 0.0f);
        #pragma unroll
        for (int o = 16; o > 0; o >>= 1) se += __shfl_xor_sync(0xffffffffu, se, o);
        float lse = mx + logf(se);
        if (lane < KC) g_logprob[b * KC + lane] = v1 - lse;
        if (lane + 32 < KC) g_logprob[b * KC + lane + 32] = v2 - lse;
    }
    // ---- last-block loss: deterministic, runs once all 64 blocks wrote ----
    __threadfence();
    __syncthreads();
    if (tid == 0) last_sh = (atomicAdd(&g_hc, 1u) == (unsigned)(BB - 1));
    __syncthreads();
    if (!last_sh) return;
    __threadfence();

    __shared__ int counts[KC];
    __shared__ float rn[8], rd[8];
    if (tid < KC) counts[tid] = 0;
    __syncthreads();
    int yi[2]; float vv[2]; int ii[2];
    #pragma unroll
    for (int u = 0; u < 2; u++) {
        int p = tid + u * 256;
        int i = g_i[p], j = g_j[p];
        float valid = g_valid[p];
        int a = labels0[i], c = labels0[j];
        int y;
        if (a == c) y = 0;
        else {
            int lo = min(a, c), hi = max(a, c);
            y = 1 + lo * 9 - (lo * (lo - 1)) / 2 + (hi - lo - 1);
        }
        yi[u] = y; vv[u] = valid; ii[u] = i;
        if (valid > 0.0f) atomicAdd(&counts[y], 1);
    }
    __syncthreads();
    float num = 0.0f, den = 0.0f;
    #pragma unroll
    for (int u = 0; u < 2; u++) {
        int y = yi[u];
        float cw = counts[y] > 0 ? 1.0f / (float)counts[y] : 0.0f;
        float wy = cw * vv[u];
        num += wy * (-g_logprob[ii[u] * KC + y]);
        den += wy;
    }
    int lane3 = tid & 31, w3 = tid >> 5;
    #pragma unroll
    for (int o = 16; o > 0; o >>= 1) {
        num += __shfl_down_sync(0xffffffffu, num, o);
        den += __shfl_down_sync(0xffffffffu, den, o);
    }
    if (lane3 == 0) { rn[w3] = num; rd[w3] = den; }
    __syncthreads();
    if (tid == 0) {
        float n2 = 0.0f, d2 = 0.0f;
        #pragma unroll
        for (int t = 0; t < 8; t++) { n2 += rn[t]; d2 += rd[t]; }
        out[0] = n2 / d2;
    }
}

// ---------------------------------------------------------------------------
extern "C" void kernel_launch(void* const* d_in, const int* in_sizes, int n_in,
                              void* d_out, int out_size) {
    const float* feat    = (const float*)d_in[0];
    const int*   labels0 = (const int*)d_in[1];
    const int*   labels1 = (const int*)d_in[2];
    const float* ipw     = (const float*)d_in[3];
    const float* ipb     = (const float*)d_in[4];
    const float* opw     = (const float*)d_in[5];
    const float* opb     = (const float*)d_in[6];
    const float* fw      = (const float*)d_in[7];
    const float* fbv     = (const float*)d_in[8];
    const float* hw      = (const float*)d_in[9];
    const float* hbv     = (const float*)d_in[10];
    float* out = (float*)d_out;

    setup_kernel<<<161, 256>>>(feat, ipw, labels1);
    dim3 g(16, 8);                            // one wave: 128 blocks
    qkv_mma<<<g, 256>>>(ipb);
    attn_kernel<<<SS * HH, 64>>>(fw);         // 512 blocks, writes g_G via RED
    head_kernel<<<BB, 256>>>(opw, opb, fw, fbv, hw, hbv, labels0, out);
}

// round 12
// speedup vs baseline: 1.1222x; 1.1058x over previous
#include <cuda_runtime.h>
#include <math.h>
#include <stdint.h>

#define BB 64      // batch
#define EE 256     // embed
#define SS 32      // seq
#define HH 16      // heads
#define HD 16      // head dim
#define PP 512     // pairs
#define KC 46      // classes
#define MROWS (BB*SS)   // 2048
#define NCOLS (3*EE)    // 768
#define NMT (MROWS/16)  // 128 m-tiles
#define NNT (NCOLS/8)   // 96 n-tiles
#define NKS (EE/8)      // 32 k-steps

// ---------------- scratch (device globals; no allocation allowed) ----------
__device__ __align__(16) float g_Afrag[NMT * NKS * 32 * 8];  // canned A frags (hi4,lo4)
__device__ __align__(16) float g_Bfrag[NNT * NKS * 32 * 4];  // canned B frags
__device__ __align__(16) float g_QKV[MROWS * NCOLS];
__device__ __align__(16) float g_O[BB * SS * EE];
__device__ __align__(16) float g_logprob[BB * KC];
__device__ int   g_i[PP], g_j[PP];
__device__ float g_valid[PP];
__device__ float g_cj[BB];
__device__ int   g_sel[PP];
__device__ unsigned g_hc;          // head-block completion counter (reset by setup)

__device__ __forceinline__ void split_tf32(float x, float& hi, float& lo) {
    uint32_t u;
    asm("cvt.rna.tf32.f32 %0, %1;" : "=r"(u) : "f"(x));
    hi = __uint_as_float(u);
    float r = x - hi;
    asm("cvt.rna.tf32.f32 %0, %1;" : "=r"(u) : "f"(r));
    lo = __uint_as_float(u);
}

__device__ __forceinline__ void mma_tf32(float c[4], float a0, float a1, float a2, float a3,
                                         float b0, float b1) {
    asm volatile(
        "mma.sync.aligned.m16n8k8.row.col.f32.tf32.tf32.f32 "
        "{%0,%1,%2,%3}, {%4,%5,%6,%7}, {%8,%9}, {%0,%1,%2,%3};"
        : "+f"(c[0]), "+f"(c[1]), "+f"(c[2]), "+f"(c[3])
        : "r"(__float_as_uint(a0)), "r"(__float_as_uint(a1)),
          "r"(__float_as_uint(a2)), "r"(__float_as_uint(a3)),
          "r"(__float_as_uint(b0)), "r"(__float_as_uint(b1)));
}

// ---------------- 1) fused setup: A-split | B-split(x2) | pair scan --------
// 113 blocks = one wave: 0..63 A-units, 64..111 two B-units each, 112 pairs.
__global__ void __launch_bounds__(256) setup_kernel(const float* __restrict__ feat,
                                                    const float* __restrict__ W,
                                                    const int* __restrict__ labels1) {
    int tid = threadIdx.x;
    int bx = blockIdx.x;
    if (bx < 64) {
        // ---- A split: A[m][k] = feat[b, k, s], m = b*32+s ----
        __shared__ float sA[256][33];
        int b = bx;
        int s = tid & 31, k0 = tid >> 5;
        for (int k = k0; k < 256; k += 8)
            sA[k][s] = feat[b * 8192 + k * 32 + s];
        __syncthreads();
        #pragma unroll
        for (int t = 0; t < 8; t++) {
            int idx = t * 256 + tid;
            int mt_l = idx >> 10;
            int rem = idx & 1023;
            int ks = rem >> 5, lane = rem & 31;
            int g = lane >> 2, tg = lane & 3;
            int r0 = mt_l * 16 + g;
            int k1 = ks * 8 + tg, k2 = k1 + 4;
            float a0 = sA[k1][r0], a1 = sA[k1][r0 + 8];
            float a2 = sA[k2][r0], a3 = sA[k2][r0 + 8];
            float h0, l0, h1, l1, h2, l2, h3, l3;
            split_tf32(a0, h0, l0); split_tf32(a1, h1, l1);
            split_tf32(a2, h2, l2); split_tf32(a3, h3, l3);
            int mt = b * 2 + mt_l;
            float4* dst = (float4*)&g_Afrag[((mt * NKS + ks) * 32 + lane) * 8];
            dst[0] = make_float4(h0, h1, h2, h3);
            dst[1] = make_float4(l0, l1, l2, l3);
        }
    } else if (bx < 112) {
        // ---- B split: 2 n-tiles per block ----
        __shared__ float sW[8][260];
        #pragma unroll
        for (int it = 0; it < 2; it++) {
            int nt = (bx - 64) * 2 + it;
            if (it) __syncthreads();
            int row = tid >> 5;
            int kk = (tid & 31) * 8;
            const float* wr = W + (nt * 8 + row) * 256 + kk;
            #pragma unroll
            for (int u = 0; u < 8; u++) sW[row][kk + u] = wr[u];
            __syncthreads();
            #pragma unroll
            for (int t = 0; t < 4; t++) {
                int idx = t * 256 + tid;
                int ks = idx >> 5, lane = idx & 31;
                int g = lane >> 2, tg = lane & 3;
                float b0 = sW[g][ks * 8 + tg], b1 = sW[g][ks * 8 + 4 + tg];
                float h0, l0, h1, l1;
                split_tf32(b0, h0, l0);
                split_tf32(b1, h1, l1);
                ((float4*)g_Bfrag)[(nt * NKS + ks) * 32 + lane] = make_float4(h0, h1, l0, l1);
            }
        }
    } else {
        // ---- pair setup ----
        __shared__ int l1[BB];
        __shared__ int cnt[256];
        __shared__ int off[257];
        __shared__ int cj[BB];
        if (tid == 0) g_hc = 0;          // reset completion counter every launch
        if (tid < BB) { l1[tid] = labels1[tid]; cj[tid] = 0; }
        __syncthreads();
        int base = tid * 16;
        int c = 0;
        #pragma unroll
        for (int u = 0; u < 16; u++) {
            int idx = base + u;
            c += (l1[idx >> 6] == l1[idx & 63]);
        }
        cnt[tid] = c;
        __syncthreads();
        if (tid == 0) {
            int acc = 0;
            for (int t = 0; t < 256; t++) { off[t] = acc; acc += cnt[t]; }
            off[256] = acc;
        }
        __syncthreads();
        int pos = off[tid];
        #pragma unroll
        for (int u = 0; u < 16; u++) {
            int idx = base + u;
            if (l1[idx >> 6] == l1[idx & 63]) {
                if (pos < PP) g_sel[pos] = idx;
                pos++;
            }
        }
        int total = off[256];
        for (int p2 = total + tid; p2 < PP; p2 += 256) g_sel[p2] = 0;
        __syncthreads();
        int nv = total < PP ? total : PP;
        for (int p = tid; p < PP; p += 256) {
            int s0 = g_sel[p];
            int i = s0 >> 6, j = s0 & 63;
            g_i[p] = i; g_j[p] = j;
            g_valid[p] = (p < nv) ? 1.0f : 0.0f;
            atomicAdd(&cj[j], 1);
        }
        __syncthreads();
        if (tid < BB) g_cj[tid] = (float)cj[tid];
    }
}

// ---------------- 2) QKV GEMM: one-wave fragment-direct tf32x3 -------------
// 128 blocks (16x8), block tile 128(M) x 96(N); warp tile 32x48; no smem.
__global__ void __launch_bounds__(256, 1) qkv_mma(const float* __restrict__ bias) {
    int bx = blockIdx.x;   // 0..15 (M)
    int by = blockIdx.y;   // 0..7  (N)
    int tid = threadIdx.x, warp = tid >> 5, lane = tid & 31;
    int g = lane >> 2, tg = lane & 3;
    int wr = warp >> 1, wc = warp & 1;
    int mtb = bx * 8 + wr * 2;     // 2 m-tiles per warp
    int ntb = by * 12 + wc * 6;    // 6 n-tiles per warp
    float c[2][6][4] = {};
    const float4* Af = (const float4*)g_Afrag;
    const float4* Bf = (const float4*)g_Bfrag;
    #pragma unroll 2
    for (int ks = 0; ks < NKS; ks++) {
        float4 ah[2], al[2], bf[6];
        #pragma unroll
        for (int mi = 0; mi < 2; mi++) {
            int ia = (((mtb + mi) * NKS + ks) * 32 + lane) * 2;
            ah[mi] = Af[ia];
            al[mi] = Af[ia + 1];
        }
        #pragma unroll
        for (int ni = 0; ni < 6; ni++)
            bf[ni] = Bf[((ntb + ni) * NKS + ks) * 32 + lane];
        #pragma unroll
        for (int mi = 0; mi < 2; mi++)
            #pragma unroll
            for (int ni = 0; ni < 6; ni++) {
                mma_tf32(c[mi][ni], ah[mi].x, ah[mi].y, ah[mi].z, ah[mi].w, bf[ni].x, bf[ni].y);
                mma_tf32(c[mi][ni], ah[mi].x, ah[mi].y, ah[mi].z, ah[mi].w, bf[ni].z, bf[ni].w);
                mma_tf32(c[mi][ni], al[mi].x, al[mi].y, al[mi].z, al[mi].w, bf[ni].x, bf[ni].y);
            }
    }
    #pragma unroll
    for (int mi = 0; mi < 2; mi++) {
        int m = bx * 128 + wr * 32 + mi * 16 + g;
        #pragma unroll
        for (int ni = 0; ni < 6; ni++) {
            int n = by * 96 + wc * 48 + ni * 8 + 2 * tg;
            float b0 = bias[n], b1 = bias[n + 1];
            *(float2*)(g_QKV + m * NCOLS + n) = make_float2(c[mi][ni][0] + b0, c[mi][ni][1] + b1);
            *(float2*)(g_QKV + (m + 8) * NCOLS + n) = make_float2(c[mi][ni][2] + b0, c[mi][ni][3] + b1);
        }
    }
}

// ---------------- 3) attention per (s,h): split-j, 1-pass softmax ----------
// 128 threads: half 0 handles j in [0,32), half 1 j in [32,64); partials are
// combined through smem. Halves serial depth and doubles warps/SM vs R9.
__global__ void __launch_bounds__(128) attn_kernel() {
    int s = blockIdx.x & 31;
    int h = blockIdx.x >> 5;
    __shared__ float Ks[BB][HD];
    __shared__ float Vs[BB][HD];
    __shared__ float cjs[BB];
    __shared__ float Pd[BB];            // upper-half partial denom
    __shared__ float Pa[BB][HD + 1];    // upper-half partial acc (17: conflict-free)
    int tid = threadIdx.x;
    int half = tid >> 6;
    int b = tid & 63;

    const float* qkv_row = g_QKV + (b * SS + s) * NCOLS + h * HD;
    if (half == 0) {    // K rows + counts
        const float4* kp = (const float4*)(qkv_row + EE);
        float4* kd = (float4*)Ks[b];
        kd[0] = kp[0]; kd[1] = kp[1]; kd[2] = kp[2]; kd[3] = kp[3];
        cjs[b] = g_cj[b];
    } else {            // V rows
        const float4* vp = (const float4*)(qkv_row + 2 * EE);
        float4* vd = (float4*)Vs[b];
        vd[0] = vp[0]; vd[1] = vp[1]; vd[2] = vp[2]; vd[3] = vp[3];
    }
    float4 q0 = ((const float4*)qkv_row)[0];
    float4 q1 = ((const float4*)qkv_row)[1];
    float4 q2 = ((const float4*)qkv_row)[2];
    float4 q3 = ((const float4*)qkv_row)[3];
    __syncthreads();

    float denom = 0.0f;
    float acc[HD];
    #pragma unroll
    for (int d = 0; d < HD; d++) acc[d] = 0.0f;
    int j0 = half << 5;
    #pragma unroll 4
    for (int jj = 0; jj < 32; jj++) {
        int j = j0 + jj;
        const float4* kr = (const float4*)Ks[j];
        float4 k0 = kr[0], k1 = kr[1], k2 = kr[2], k3 = kr[3];
        float p0 = q0.x * k0.x + q0.y * k0.y + q0.z * k0.z + q0.w * k0.w;
        float p1 = q1.x * k1.x + q1.y * k1.y + q1.z * k1.z + q1.w * k1.w;
        float p2 = q2.x * k2.x + q2.y * k2.y + q2.z * k2.z + q2.w * k2.w;
        float p3 = q3.x * k3.x + q3.y * k3.y + q3.z * k3.z + q3.w * k3.w;
        float sc = ((p0 + p1) + (p2 + p3)) * 0.25f;
        float p = cjs[j] * __expf(sc);     // scores O(1): no max pass (validated R7+)
        denom += p;
        const float4* vr = (const float4*)Vs[j];
        float4 v0 = vr[0], v1 = vr[1], v2 = vr[2], v3 = vr[3];
        acc[0] += p * v0.x;  acc[1] += p * v0.y;  acc[2] += p * v0.z;  acc[3] += p * v0.w;
        acc[4] += p * v1.x;  acc[5] += p * v1.y;  acc[6] += p * v1.z;  acc[7] += p * v1.w;
        acc[8] += p * v2.x;  acc[9] += p * v2.y;  acc[10] += p * v2.z; acc[11] += p * v2.w;
        acc[12] += p * v3.x; acc[13] += p * v3.y; acc[14] += p * v3.z; acc[15] += p * v3.w;
    }
    if (half) {
        Pd[b] = denom;
        #pragma unroll
        for (int d = 0; d < HD; d++) Pa[b][d] = acc[d];
    }
    __syncthreads();
    if (!half) {
        denom += Pd[b];
        float inv = 1.0f / denom;
        float* op = g_O + (b * SS + s) * EE + h * HD;
        #pragma unroll
        for (int d = 0; d < HD; d++) op[d] = (acc[d] + Pa[b][d]) * inv;
    }
}

// ---------------- 4) head (fused seq-reduce) + (last block) loss -----------
__global__ void __launch_bounds__(256) head_kernel(const float* __restrict__ Wo,
                                                   const float* __restrict__ bo,
                                                   const float* __restrict__ fw,
                                                   const float* __restrict__ fb,
                                                   const float* __restrict__ Hw,
                                                   const float* __restrict__ hb,
                                                   const int* __restrict__ labels0,
                                                   float* __restrict__ out) {
    int b = blockIdx.x;
    __shared__ float Gs[EE];
    __shared__ float hs[EE];
    __shared__ float ls[64];
    __shared__ float fws[SS];
    __shared__ float sfw_sh;
    __shared__ unsigned last_sh;
    int tid = threadIdx.x;
    if (tid < SS) fws[tid] = fw[tid];
    __syncthreads();
    if (tid < 32) {
        float v = fws[tid];
        #pragma unroll
        for (int o = 16; o > 0; o >>= 1) v += __shfl_xor_sync(0xffffffffu, v, o);
        if (tid == 0) sfw_sh = v;
    }
    {   // G[e] — coalesced over e
        const float* ob = g_O + b * SS * EE + tid;
        float acc = 0.0f;
        #pragma unroll
        for (int s = 0; s < SS; s++) acc += ob[s * EE] * fws[s];
        Gs[tid] = acc;
    }
    __syncthreads();
    {   // h[r] = dot(G, Wo[r]) — thread-per-row, full ILP
        int r = tid;
        const float4* wrow = (const float4*)(Wo + r * EE);
        const float4* gv4 = (const float4*)Gs;
        float p = 0.0f;
        #pragma unroll 8
        for (int k = 0; k < EE / 4; k++) {
            float4 wv = wrow[k];
            float4 gv = gv4[k];
            p += wv.x * gv.x + wv.y * gv.y + wv.z * gv.z + wv.w * gv.w;
        }
        hs[r] = p + sfw_sh * bo[r] + fb[0];
    }
    __syncthreads();
    if (tid < KC) {
        const float4* hrow = (const float4*)(Hw + tid * EE);
        const float4* hv4 = (const float4*)hs;
        float p = 0.0f;
        #pragma unroll 8
        for (int k = 0; k < EE / 4; k++) {
            float4 wv = hrow[k];
            float4 hv = hv4[k];
            p += wv.x * hv.x + wv.y * hv.y + wv.z * hv.z + wv.w * hv.w;
        }
        ls[tid] = p + hb[tid];
    }
    __syncthreads();
    if (tid < 32) {
        int lane = tid;
        float v1 = (lane < KC) ? ls[lane] : -1e30f;
        float v2 = (lane + 32 < KC) ? ls[lane + 32] : -1e30f;
        float mx = fmaxf(v1, v2);
        #pragma unroll
        for (int o = 16; o > 0; o >>= 1) mx = fmaxf(mx, __shfl_xor_sync(0xffffffffu, mx, o));
        float se = ((lane < KC) ? __expf(v1 - mx) : 0.0f)
                 + ((lane + 32 < KC) ? __expf(v2 - mx) : 0.0f);
        #pragma unroll
        for (int o = 16; o > 0; o >>= 1) se += __shfl_xor_sync(0xffffffffu, se, o);
        float lse = mx + logf(se);
        if (lane < KC) g_logprob[b * KC + lane] = v1 - lse;
        if (lane + 32 < KC) g_logprob[b * KC + lane + 32] = v2 - lse;
    }
    // ---- last-block loss: deterministic, runs once all 64 blocks wrote ----
    __threadfence();
    __syncthreads();
    if (tid == 0) last_sh = (atomicAdd(&g_hc, 1u) == (unsigned)(BB - 1));
    __syncthreads();
    if (!last_sh) return;
    __threadfence();

    __shared__ int counts[KC];
    __shared__ float rn[8], rd[8];
    if (tid < KC) counts[tid] = 0;
    __syncthreads();
    int yi[2]; float vv[2]; int ii[2];
    #pragma unroll
    for (int u = 0; u < 2; u++) {
        int p = tid + u * 256;
        int i = g_i[p], j = g_j[p];
        float valid = g_valid[p];
        int a = labels0[i], c = labels0[j];
        int y;
        if (a == c) y = 0;
        else {
            int lo = min(a, c), hi = max(a, c);
            y = 1 + lo * 9 - (lo * (lo - 1)) / 2 + (hi - lo - 1);
        }
        yi[u] = y; vv[u] = valid; ii[u] = i;
        if (valid > 0.0f) atomicAdd(&counts[y], 1);
    }
    __syncthreads();
    float num = 0.0f, den = 0.0f;
    #pragma unroll
    for (int u = 0; u < 2; u++) {
        int y = yi[u];
        float cw = counts[y] > 0 ? 1.0f / (float)counts[y] : 0.0f;
        float wy = cw * vv[u];
        num += wy * (-g_logprob[ii[u] * KC + y]);
        den += wy;
    }
    int lane3 = tid & 31, w3 = tid >> 5;
    #pragma unroll
    for (int o = 16; o > 0; o >>= 1) {
        num += __shfl_down_sync(0xffffffffu, num, o);
        den += __shfl_down_sync(0xffffffffu, den, o);
    }
    if (lane3 == 0) { rn[w3] = num; rd[w3] = den; }
    __syncthreads();
    if (tid == 0) {
        float n2 = 0.0f, d2 = 0.0f;
        #pragma unroll
        for (int t = 0; t < 8; t++) { n2 += rn[t]; d2 += rd[t]; }
        out[0] = n2 / d2;
    }
}

// ---------------------------------------------------------------------------
extern "C" void kernel_launch(void* const* d_in, const int* in_sizes, int n_in,
                              void* d_out, int out_size) {
    const float* feat    = (const float*)d_in[0];
    const int*   labels0 = (const int*)d_in[1];
    const int*   labels1 = (const int*)d_in[2];
    const float* ipw     = (const float*)d_in[3];
    const float* ipb     = (const float*)d_in[4];
    const float* opw     = (const float*)d_in[5];
    const float* opb     = (const float*)d_in[6];
    const float* fw      = (const float*)d_in[7];
    const float* fbv     = (const float*)d_in[8];
    const float* hw      = (const float*)d_in[9];
    const float* hbv     = (const float*)d_in[10];
    float* out = (float*)d_out;

    setup_kernel<<<113, 256>>>(feat, ipw, labels1);   // one wave
    dim3 g(16, 8);                            // one wave: 128 blocks
    qkv_mma<<<g, 256>>>(ipb);
    attn_kernel<<<SS * HH, 128>>>();          // 512 blocks, split-j
    head_kernel<<<BB, 256>>>(opw, opb, fw, fbv, hw, hbv, labels0, out);
}